// round 10
// baseline (speedup 1.0000x reference)
#include <cuda_runtime.h>
#include <cuda_fp16.h>
#include <math.h>
#include <cstdint>

#define TOK  16384
#define HID  4096
#define NE   64
#define CTOP 512
#define EPSF 1e-6f
#define NPART 2048
#define NUNIT 4096               // 1024 bands x 4 K-quarters
#define NPAIR 592                // 148 CTAs x 4 SMSP pairs

__device__ float g_quart[4][TOK * NE];  // per-K-quarter partials (16MB)
__device__ float g_logits[TOK * NE];
__device__ float g_partT[NE * NPART];
__device__ float g_imp[NE];
__device__ uint4 g_bfrag[256 * 8 * 32]; // [k16][n8][lane] = {b0h,b1h,b0l,b1l}

// ---------------------------- helpers ---------------------------------------
__device__ __forceinline__ void mma_f32(float* c, const uint32_t* a,
                                        uint32_t b0, uint32_t b1) {
    asm volatile(
        "mma.sync.aligned.m16n8k16.row.col.f32.f16.f16.f32 "
        "{%0,%1,%2,%3}, {%4,%5,%6,%7}, {%8,%9}, {%0,%1,%2,%3};"
        : "+f"(c[0]), "+f"(c[1]), "+f"(c[2]), "+f"(c[3])
        : "r"(a[0]), "r"(a[1]), "r"(a[2]), "r"(a[3]), "r"(b0), "r"(b1));
}
__device__ __forceinline__ void mma_f16(uint32_t* c, const uint32_t* a,
                                        uint32_t b0, uint32_t b1) {
    asm volatile(
        "mma.sync.aligned.m16n8k16.row.col.f16.f16.f16.f16 "
        "{%0,%1}, {%2,%3,%4,%5}, {%6,%7}, {%0,%1};"
        : "+r"(c[0]), "+r"(c[1])
        : "r"(a[0]), "r"(a[1]), "r"(a[2]), "r"(a[3]), "r"(b0), "r"(b1));
}
__device__ __forceinline__ void split_f2(float2 v, uint32_t& h, uint32_t& l) {
    __half2 hh = __floats2half2_rn(v.x, v.y);
    float2 hf = __half22float2(hh);
    __half2 ll = __floats2half2_rn(v.x - hf.x, v.y - hf.y);
    h = *reinterpret_cast<uint32_t*>(&hh);
    l = *reinterpret_cast<uint32_t*>(&ll);
}

// ------------- pre-kernel: gate_w -> fragment-replicated hi/lo halves -------
__global__ void __launch_bounds__(256)
build_bfrag(const float* __restrict__ gate)
{
    const int idx = blockIdx.x * 256 + threadIdx.x;
    const int lane = idx & 31, n8 = (idx >> 5) & 7, k16 = idx >> 8;
    const int n = n8 * 8 + (lane >> 2);
    const int k0 = k16 * 16 + (lane & 3) * 2;
    const float* g = gate + (size_t)n * HID + k0;
    const float2 v0 = *reinterpret_cast<const float2*>(g);
    const float2 v1 = *reinterpret_cast<const float2*>(g + 8);
    uint32_t b0h, b0l, b1h, b1l;
    split_f2(v0, b0h, b0l);
    split_f2(v1, b1h, b1l);
    g_bfrag[idx] = make_uint4(b0h, b1h, b0l, b1l);
}

// === GEMM: K-split units (m16 x K/4), static SMSP-pair-balanced schedule ====
__global__ void __launch_bounds__(256, 1)
gemm_kernel(const float* __restrict__ A)
{
    const int tid = threadIdx.x, lane = tid & 31, wid = tid >> 5;
    const int pair = blockIdx.x * 4 + (wid & 3);   // 0..591 (SMSP pair id)
    const int half = wid >> 2;                     // warp lo(0)/hi(1) of pair

#pragma unroll 1
    for (int j = half; ; j += 2) {
        const int u = pair + j * NPAIR;
        if (u >= NUNIT) break;
        const int band = u >> 2, kq = u & 3;
        const int row = band * 16 + (lane >> 2);
        const float* a0 = A + (size_t)row * HID + kq * 1024 + (lane & 3) * 2;
        const float* a1 = a0 + 8 * HID;

        float accf[8][4];
        uint32_t acc16[8][2];
#pragma unroll
        for (int n = 0; n < 8; n++) {
#pragma unroll
            for (int i = 0; i < 4; i++) accf[n][i] = 0.f;
            acc16[n][0] = 0u; acc16[n][1] = 0u;
        }

        float2 cur[8], nxt[8];
#pragma unroll
        for (int ks = 0; ks < 2; ks++) {
            const int o = ks * 16;
            cur[ks * 4 + 0] = *reinterpret_cast<const float2*>(a0 + o);
            cur[ks * 4 + 1] = *reinterpret_cast<const float2*>(a1 + o);
            cur[ks * 4 + 2] = *reinterpret_cast<const float2*>(a0 + o + 8);
            cur[ks * 4 + 3] = *reinterpret_cast<const float2*>(a1 + o + 8);
        }

#pragma unroll 1
        for (int kk = 0; kk < 32; kk++) {        // 32 k32-chunks per unit
            if (kk + 1 < 32) {
                const int base = (kk + 1) * 32;
#pragma unroll
                for (int ks = 0; ks < 2; ks++) {
                    const int o = base + ks * 16;
                    nxt[ks * 4 + 0] = *reinterpret_cast<const float2*>(a0 + o);
                    nxt[ks * 4 + 1] = *reinterpret_cast<const float2*>(a1 + o);
                    nxt[ks * 4 + 2] = *reinterpret_cast<const float2*>(a0 + o + 8);
                    nxt[ks * 4 + 3] = *reinterpret_cast<const float2*>(a1 + o + 8);
                }
            }
            const int ktg = kq * 32 + kk;        // global k32 index
#pragma unroll
            for (int ks = 0; ks < 2; ks++) {
                uint32_t ah[4], al[4];
#pragma unroll
                for (int jj = 0; jj < 4; jj++)
                    split_f2(cur[ks * 4 + jj], ah[jj], al[jj]);
                uint4 b[8];
                const uint4* bp = g_bfrag + ((size_t)(ktg * 2 + ks) * 8) * 32 + lane;
#pragma unroll
                for (int n8 = 0; n8 < 8; n8++) b[n8] = __ldg(&bp[n8 * 32]);
                // reordered: sweep each term across n8 (RAW distance = 8)
#pragma unroll
                for (int n8 = 0; n8 < 8; n8++) mma_f32(accf[n8], ah, b[n8].x, b[n8].y);
#pragma unroll
                for (int n8 = 0; n8 < 8; n8++) mma_f16(acc16[n8], ah, b[n8].z, b[n8].w);
#pragma unroll
                for (int n8 = 0; n8 < 8; n8++) mma_f16(acc16[n8], al, b[n8].x, b[n8].y);
            }
            if ((kk & 3) == 3) {                 // promote fp16 corrections
#pragma unroll
                for (int n = 0; n < 8; n++) {
                    const float2 lo = __half22float2(*reinterpret_cast<__half2*>(&acc16[n][0]));
                    const float2 hi = __half22float2(*reinterpret_cast<__half2*>(&acc16[n][1]));
                    accf[n][0] += lo.x; accf[n][1] += lo.y;
                    accf[n][2] += hi.x; accf[n][3] += hi.y;
                    acc16[n][0] = 0u; acc16[n][1] = 0u;
                }
            }
#pragma unroll
            for (int jj = 0; jj < 8; jj++) cur[jj] = nxt[jj];
        }

        // epilogue: write this unit's partial (32 % 4 == 0 -> fully promoted)
        const int gid = lane >> 2, col = (lane & 3) * 2;
        const int row0 = band * 16 + gid;
        float* q = g_quart[kq];
#pragma unroll
        for (int n = 0; n < 8; n++) {
            *reinterpret_cast<float2*>(&q[row0 * NE + n * 8 + col]) =
                make_float2(accf[n][0], accf[n][1]);
            *reinterpret_cast<float2*>(&q[(row0 + 8) * NE + n * 8 + col]) =
                make_float2(accf[n][2], accf[n][3]);
        }
    }
}

// ------------------- combine: logits = q0+q1+q2+q3 (fixed order) ------------
__global__ void __launch_bounds__(256)
combine_kernel()
{
    const int i = blockIdx.x * 256 + threadIdx.x;   // 262144 float4 slots
    const float4 a = reinterpret_cast<const float4*>(g_quart[0])[i];
    const float4 b = reinterpret_cast<const float4*>(g_quart[1])[i];
    const float4 c = reinterpret_cast<const float4*>(g_quart[2])[i];
    const float4 d = reinterpret_cast<const float4*>(g_quart[3])[i];
    reinterpret_cast<float4*>(g_logits)[i] =
        make_float4(((a.x + b.x) + c.x) + d.x, ((a.y + b.y) + c.y) + d.y,
                    ((a.z + b.z) + c.z) + d.z, ((a.w + b.w) + c.w) + d.w);
}

// ===================== top-C per expert (smem-cached radix select) ==========
__device__ __forceinline__ unsigned omap(float f) {
    unsigned u = __float_as_uint(f);
    return (u & 0x80000000u) ? ~u : (u | 0x80000000u);
}
__global__ void __launch_bounds__(256)
topk_kernel(float* __restrict__ routing)
{
    extern __shared__ unsigned keys[];          // TOK uints (64KB)
    __shared__ unsigned hist[256];
    __shared__ unsigned tlist[256];
    __shared__ unsigned s_pref, s_rem, s_tc;
    const int e = blockIdx.x, tid = threadIdx.x;

    for (int t = tid; t < TOK; t += 256)
        keys[t] = omap(g_logits[t * NE + e]);
    if (tid == 0) { s_pref = 0u; s_rem = CTOP; s_tc = 0u; }

    for (int b = 3; b >= 0; b--) {
        __syncthreads();
        hist[tid] = 0u;
        __syncthreads();
        const unsigned pref = s_pref;
        for (int t = tid; t < TOK; t += 256) {
            const unsigned u = keys[t];
            const bool ok = (b == 3) || ((u >> (((b + 1) & 3) * 8)) == pref);
            if (ok) atomicAdd(&hist[(u >> (b * 8)) & 255u], 1u);
        }
        __syncthreads();
        if (tid == 0) {
            unsigned rem = s_rem, cum = 0u;
            int d = 255;
            for (; d > 0; d--) { cum += hist[d]; if (cum >= rem) break; }
            if (cum < rem) { cum += hist[0]; d = 0; }
            s_rem = rem - (cum - hist[d]);
            s_pref = (pref << 8) | (unsigned)d;
        }
    }
    __syncthreads();
    const unsigned tkey = s_pref;
    for (int t = tid; t < TOK; t += 256) {
        const unsigned u = keys[t];
        float r = 0.f;
        if (u > tkey) r = 1.f;
        else if (u == tkey) {
            const unsigned p = atomicAdd(&s_tc, 1u);
            if (p < 256u) tlist[p] = (unsigned)t;
        }
        routing[(size_t)t * NE + e] = r;
    }
    __syncthreads();
    if (tid == 0) {
        int n = (int)s_tc; if (n > 256) n = 256;
        for (int i = 1; i < n; i++) {
            const unsigned v = tlist[i]; int j = i - 1;
            while (j >= 0 && tlist[j] > v) { tlist[j + 1] = tlist[j]; j--; }
            tlist[j + 1] = v;
        }
        int take = (int)s_rem; if (take > n) take = n;
        for (int i = 0; i < take; i++)
            routing[(size_t)tlist[i] * NE + e] = 1.f;
    }
}

// ============ softmax + mask + renorm; loads hoisted ahead of reductions ====
__global__ void __launch_bounds__(256)
softmax_kernel(const float* __restrict__ routing, float* __restrict__ probs)
{
    const int lane = threadIdx.x & 31, w = threadIdx.x >> 5;
    const int t = blockIdx.x * 8 + w;
    __shared__ float sA[8][32], sB[8][32];

    const float l0 = g_logits[t * NE + lane];
    const float l1 = g_logits[t * NE + 32 + lane];
    const float r0 = routing[(size_t)t * NE + lane];
    const float r1 = routing[(size_t)t * NE + 32 + lane];
    float m = fmaxf(l0, l1);
#pragma unroll
    for (int o = 16; o; o >>= 1) m = fmaxf(m, __shfl_xor_sync(~0u, m, o));
    const float e0 = __expf(l0 - m), e1 = __expf(l1 - m);
    float s = e0 + e1;
#pragma unroll
    for (int o = 16; o; o >>= 1) s += __shfl_xor_sync(~0u, s, o);
    const float q0 = (e0 / s) * r0;
    const float q1 = (e1 / s) * r1;
    float rs = q0 + q1;
#pragma unroll
    for (int o = 16; o; o >>= 1) rs += __shfl_xor_sync(~0u, rs, o);
    const float inv = 1.f / (rs + EPSF);
    const float n0 = q0 * inv, n1 = q1 * inv;
    probs[(size_t)t * NE + lane] = n0;
    probs[(size_t)t * NE + 32 + lane] = n1;

    sA[w][lane] = n0; sB[w][lane] = n1;
    __syncthreads();
    if (w == 0) {
        float a = 0.f;
#pragma unroll
        for (int k = 0; k < 8; k++) a += sA[k][lane];
        g_partT[lane * NPART + blockIdx.x] = a;
    } else if (w == 1) {
        float a = 0.f;
#pragma unroll
        for (int k = 0; k < 8; k++) a += sB[k][lane];
        g_partT[(32 + lane) * NPART + blockIdx.x] = a;
    }
}

// ===================== aux loss (coalesced importance reduce) ===============
__global__ void __launch_bounds__(256)
imp_kernel()
{
    __shared__ float red[8];
    const int e = blockIdx.x, tid = threadIdx.x;
    float s = 0.f;
    for (int i = tid; i < NPART; i += 256) s += g_partT[e * NPART + i];
#pragma unroll
    for (int o = 16; o; o >>= 1) s += __shfl_xor_sync(~0u, s, o);
    if ((tid & 31) == 0) red[tid >> 5] = s;
    __syncthreads();
    if (tid == 0) {
        float a = 0.f;
#pragma unroll
        for (int k = 0; k < 8; k++) a += red[k];
        g_imp[e] = a;
    }
}
__global__ void __launch_bounds__(64)
loss_kernel(float* __restrict__ aux)
{
    __shared__ float v[64];
    v[threadIdx.x] = g_imp[threadIdx.x];
    __syncthreads();
    if (threadIdx.x == 0) {
        float m = 0.f;
        for (int i = 0; i < 64; i++) m += v[i];
        m *= (1.f / 64.f);
        float var = 0.f;
        for (int i = 0; i < 64; i++) { const float d = v[i] - m; var += d * d; }
        var *= (1.f / 63.f);
        const float r = sqrtf(var) / (m + EPSF);
        aux[0] = r * r;   // load std == 0 exactly -> load_loss == 0
    }
}

extern "C" void kernel_launch(void* const* d_in, const int* in_sizes, int n_in,
                              void* d_out, int out_size)
{
    const float* hidden = (const float*)d_in[0];
    const float* gate   = (const float*)d_in[1];
    float* probs   = (float*)d_out;
    float* routing = probs + (size_t)TOK * NE;
    float* aux     = routing + (size_t)TOK * NE;

    cudaFuncSetAttribute(topk_kernel,
                         cudaFuncAttributeMaxDynamicSharedMemorySize, TOK * 4);

    build_bfrag<<<256, 256>>>(gate);
    gemm_kernel<<<148, 256>>>(hidden);
    combine_kernel<<<(TOK * NE / 4) / 256, 256>>>();
    topk_kernel<<<NE, 256, TOK * 4>>>(routing);
    softmax_kernel<<<TOK / 8, 256>>>(routing, probs);
    imp_kernel<<<NE, 256>>>();
    loss_kernel<<<1, 64>>>(aux);
}

// round 11
// speedup vs baseline: 1.3296x; 1.3296x over previous
#include <cuda_runtime.h>
#include <cuda_fp16.h>
#include <math.h>
#include <cstdint>

#define TOK  16384
#define HID  4096
#define NE   64
#define CTOP 512
#define EPSF 1e-6f

#define BM   128
#define NKT  (HID / 32)
#define NPART 2048
#define STG  4
#define STGU 512

__device__ float g_logits[TOK * NE];
__device__ float g_partT[NE * NPART];
__device__ float g_imp[NE];
__device__ uint4 g_bfrag[256 * 8 * 32];
__device__ unsigned g_keysT[NE * TOK];   // omap keys, transposed [e][t]
__device__ unsigned g_hist[NE * 256];    // first-pass histograms

// ---------------------------- helpers ---------------------------------------
__device__ __forceinline__ uint32_t smem_u32(const void* p) {
    uint32_t a;
    asm("{ .reg .u64 t; cvta.to.shared.u64 t, %1; cvt.u32.u64 %0, t; }"
        : "=r"(a) : "l"(p));
    return a;
}
__device__ __forceinline__ void cp16(uint32_t s, const void* g) {
    asm volatile("cp.async.cg.shared.global [%0], [%1], 16;" :: "r"(s), "l"(g));
}
#define CP_COMMIT() asm volatile("cp.async.commit_group;" ::: "memory")
#define CP_WAIT2()  asm volatile("cp.async.wait_group 2;" ::: "memory")
__device__ __forceinline__ void mma_f32(float* c, const uint32_t* a,
                                        uint32_t b0, uint32_t b1) {
    asm volatile(
        "mma.sync.aligned.m16n8k16.row.col.f32.f16.f16.f32 "
        "{%0,%1,%2,%3}, {%4,%5,%6,%7}, {%8,%9}, {%0,%1,%2,%3};"
        : "+f"(c[0]), "+f"(c[1]), "+f"(c[2]), "+f"(c[3])
        : "r"(a[0]), "r"(a[1]), "r"(a[2]), "r"(a[3]), "r"(b0), "r"(b1));
}
__device__ __forceinline__ void mma_f16(uint32_t* c, const uint32_t* a,
                                        uint32_t b0, uint32_t b1) {
    asm volatile(
        "mma.sync.aligned.m16n8k16.row.col.f16.f16.f16.f16 "
        "{%0,%1}, {%2,%3,%4,%5}, {%6,%7}, {%0,%1};"
        : "+r"(c[0]), "+r"(c[1])
        : "r"(a[0]), "r"(a[1]), "r"(a[2]), "r"(a[3]), "r"(b0), "r"(b1));
}
__device__ __forceinline__ void split_f2(float2 v, uint32_t& h, uint32_t& l) {
    __half2 hh = __floats2half2_rn(v.x, v.y);
    float2 hf = __half22float2(hh);
    __half2 ll = __floats2half2_rn(v.x - hf.x, v.y - hf.y);
    h = *reinterpret_cast<uint32_t*>(&hh);
    l = *reinterpret_cast<uint32_t*>(&ll);
}
__device__ __forceinline__ unsigned omap(float f) {
    unsigned u = __float_as_uint(f);
    return (u & 0x80000000u) ? ~u : (u | 0x80000000u);
}

// ------------- pre-kernel: gate_w -> fragment-replicated hi/lo halves -------
__global__ void __launch_bounds__(256)
build_bfrag(const float* __restrict__ gate)
{
    const int idx = blockIdx.x * 256 + threadIdx.x;
    const int lane = idx & 31, n8 = (idx >> 5) & 7, k16 = idx >> 8;
    const int n = n8 * 8 + (lane >> 2);
    const int k0 = k16 * 16 + (lane & 3) * 2;
    const float* g = gate + (size_t)n * HID + k0;
    const float2 v0 = *reinterpret_cast<const float2*>(g);
    const float2 v1 = *reinterpret_cast<const float2*>(g + 8);
    uint32_t b0h, b0l, b1h, b1l;
    split_f2(v0, b0h, b0l);
    split_f2(v1, b1h, b1l);
    g_bfrag[idx] = make_uint4(b0h, b1h, b0l, b1l);
}

// GEMM (R9-proven): 3xFP16 mma; hi*hi fp32-acc, corrections fp16-acc
__global__ void __launch_bounds__(256, 1)
gemm_kernel(const float* __restrict__ A)
{
    extern __shared__ uint4 bsm[];
    const int tid = threadIdx.x, lane = tid & 31, wid = tid >> 5;
    const int bm0 = blockIdx.x * BM;
    const int row = bm0 + wid * 16 + (lane >> 2);
    const uint32_t smb = smem_u32(bsm);

    const float* a0 = A + (size_t)row * HID + (lane & 3) * 2;
    const float* a1 = a0 + 8 * HID;

    float accf[8][4];
    uint32_t acc16[8][2];
#pragma unroll
    for (int n = 0; n < 8; n++) {
#pragma unroll
        for (int i = 0; i < 4; i++) accf[n][i] = 0.f;
        acc16[n][0] = 0u; acc16[n][1] = 0u;
    }
#pragma unroll
    for (int kt = 0; kt < 3; kt++) {
        const uint32_t dst = smb + (uint32_t)(((kt & 3) * STGU + tid) * 16);
        const uint4* src = g_bfrag + (size_t)kt * STGU + tid;
        cp16(dst, src);
        cp16(dst + 256 * 16, src + 256);
        CP_COMMIT();
    }
    float2 cur[8], nxt[8];
#pragma unroll
    for (int ks = 0; ks < 2; ks++) {
        const int o = ks * 16;
        cur[ks * 4 + 0] = *reinterpret_cast<const float2*>(a0 + o);
        cur[ks * 4 + 1] = *reinterpret_cast<const float2*>(a1 + o);
        cur[ks * 4 + 2] = *reinterpret_cast<const float2*>(a0 + o + 8);
        cur[ks * 4 + 3] = *reinterpret_cast<const float2*>(a1 + o + 8);
    }
#pragma unroll 1
    for (int kt = 0; kt < NKT; kt++) {
        if (kt + 1 < NKT) {
            const int base = (kt + 1) * 32;
#pragma unroll
            for (int ks = 0; ks < 2; ks++) {
                const int o = base + ks * 16;
                nxt[ks * 4 + 0] = *reinterpret_cast<const float2*>(a0 + o);
                nxt[ks * 4 + 1] = *reinterpret_cast<const float2*>(a1 + o);
                nxt[ks * 4 + 2] = *reinterpret_cast<const float2*>(a0 + o + 8);
                nxt[ks * 4 + 3] = *reinterpret_cast<const float2*>(a1 + o + 8);
            }
        }
        CP_WAIT2();
        __syncthreads();
        if (kt + 3 < NKT) {
            const uint32_t dst = smb + (uint32_t)((((kt + 3) & 3) * STGU + tid) * 16);
            const uint4* src = g_bfrag + (size_t)(kt + 3) * STGU + tid;
            cp16(dst, src);
            cp16(dst + 256 * 16, src + 256);
        }
        CP_COMMIT();
        const uint32_t stage = smb + (uint32_t)((kt & 3) * STGU * 16);
#pragma unroll
        for (int ks = 0; ks < 2; ks++) {
            uint32_t ah[4], al[4];
#pragma unroll
            for (int j = 0; j < 4; j++)
                split_f2(cur[ks * 4 + j], ah[j], al[j]);
            const uint32_t bbase = stage + (uint32_t)(((ks * 8) * 32 + lane) * 16);
#pragma unroll
            for (int n8 = 0; n8 < 8; n8++) {
                uint4 b;
                asm volatile("ld.shared.v4.u32 {%0,%1,%2,%3}, [%4];"
                             : "=r"(b.x), "=r"(b.y), "=r"(b.z), "=r"(b.w)
                             : "r"(bbase + (uint32_t)(n8 * 32 * 16)));
                mma_f32(accf[n8], ah, b.x, b.y);
                mma_f16(acc16[n8], ah, b.z, b.w);
                mma_f16(acc16[n8], al, b.x, b.y);
            }
        }
        if ((kt & 3) == 3) {
#pragma unroll
            for (int n = 0; n < 8; n++) {
                const float2 lo = __half22float2(*reinterpret_cast<__half2*>(&acc16[n][0]));
                const float2 hi = __half22float2(*reinterpret_cast<__half2*>(&acc16[n][1]));
                accf[n][0] += lo.x; accf[n][1] += lo.y;
                accf[n][2] += hi.x; accf[n][3] += hi.y;
                acc16[n][0] = 0u; acc16[n][1] = 0u;
            }
        }
#pragma unroll
        for (int j = 0; j < 8; j++) cur[j] = nxt[j];
    }
    const int gid = lane >> 2;
    const int col = (lane & 3) * 2;
    const int row0 = bm0 + wid * 16 + gid;
#pragma unroll
    for (int n = 0; n < 8; n++) {
        *reinterpret_cast<float2*>(&g_logits[row0 * NE + n * 8 + col]) =
            make_float2(accf[n][0], accf[n][1]);
        *reinterpret_cast<float2*>(&g_logits[(row0 + 8) * NE + n * 8 + col]) =
            make_float2(accf[n][2], accf[n][3]);
    }
}

// -------- transpose + omap: g_keysT[e][t]; also zero g_hist ------------------
__global__ void __launch_bounds__(256)
transpose_kernel()
{
    __shared__ float tile[64][65];
    const int t0 = blockIdx.x * 64;
    const int tid = threadIdx.x;
    if (blockIdx.x < NE)
        for (int i = tid; i < 256; i += 256)
            g_hist[blockIdx.x * 256 + i] = 0u;
#pragma unroll
    for (int i = 0; i < 16; i++) {
        const int idx = i * 256 + tid;
        tile[idx >> 6][idx & 63] =
            g_logits[(size_t)(t0 + (idx >> 6)) * NE + (idx & 63)];
    }
    __syncthreads();
#pragma unroll
    for (int i = 0; i < 16; i++) {
        const int idx = i * 256 + tid;
        const int e = idx >> 6, t = idx & 63;
        g_keysT[(size_t)e * TOK + t0 + t] = omap(tile[t][e]);
    }
}

// -------- split first-pass histogram (top byte), 8 blocks per expert --------
__global__ void __launch_bounds__(256)
histA_kernel()
{
    __shared__ unsigned h[256];
    const int e = blockIdx.x >> 3, q = blockIdx.x & 7;
    const int tid = threadIdx.x;
    h[tid] = 0u;
    __syncthreads();
    const unsigned* keys = g_keysT + (size_t)e * TOK + q * (TOK / 8);
#pragma unroll
    for (int i = 0; i < (TOK / 8) / 256; i++)
        atomicAdd(&h[keys[i * 256 + tid] >> 24], 1u);
    __syncthreads();
    atomicAdd(&g_hist[e * 256 + tid], h[tid]);
}

// -------- radix select with parallel suffix scans; exact ties by low idx ----
__global__ void __launch_bounds__(1024)
select_kernel(float* __restrict__ routing)
{
    __shared__ unsigned h[256], ca[256], cb[256];
    __shared__ unsigned tlist[256];
    __shared__ unsigned s_pref, s_rem, s_tc;
    const int e = blockIdx.x, tid = threadIdx.x;
    const unsigned* keys = g_keysT + (size_t)e * TOK;

    if (tid == 0) { s_rem = CTOP; s_tc = 0u; }
    if (tid < 256) h[tid] = g_hist[e * 256 + tid];
    __syncthreads();

    for (int b = 3; b >= 0; b--) {
        if (b < 3) {
            if (tid < 256) h[tid] = 0u;
            __syncthreads();
            const unsigned pref = s_pref;
            const int shift = (b + 1) * 8;
            for (int i = 0; i < TOK / 1024; i++) {
                const unsigned u = keys[i * 1024 + tid];
                if ((u >> shift) == pref)
                    atomicAdd(&h[(u >> (b * 8)) & 255u], 1u);
            }
            __syncthreads();
        }
        if (tid < 256) ca[tid] = h[tid];
        __syncthreads();
        unsigned* src = ca; unsigned* dst = cb;
        for (int s = 1; s < 256; s <<= 1) {
            if (tid < 256)
                dst[tid] = src[tid] + ((tid + s < 256) ? src[tid + s] : 0u);
            __syncthreads();
            unsigned* tmp = src; src = dst; dst = tmp;
        }
        if (tid < 256) {
            const unsigned rem = s_rem;
            const unsigned cd = src[tid];
            const unsigned cn = (tid < 255) ? src[tid + 1] : 0u;
            if (cd >= rem && cn < rem) {
                s_pref = (b == 3) ? (unsigned)tid
                                  : ((s_pref << 8) | (unsigned)tid);
                s_rem = rem - cn;
            }
        }
        __syncthreads();
    }

    const unsigned tkey = s_pref;
    for (int i = 0; i < TOK / 1024; i++) {
        const int t = i * 1024 + tid;
        const unsigned u = keys[t];
        float r = 0.f;
        if (u > tkey) r = 1.f;
        else if (u == tkey) {
            const unsigned p = atomicAdd(&s_tc, 1u);
            if (p < 256u) tlist[p] = (unsigned)t;
        }
        routing[(size_t)t * NE + e] = r;
    }
    __syncthreads();
    if (tid == 0) {
        int n = (int)s_tc; if (n > 256) n = 256;
        for (int i = 1; i < n; i++) {
            const unsigned v = tlist[i]; int j = i - 1;
            while (j >= 0 && tlist[j] > v) { tlist[j + 1] = tlist[j]; j--; }
            tlist[j + 1] = v;
        }
        int take = (int)s_rem; if (take > n) take = n;
        for (int i = 0; i < take; i++)
            routing[(size_t)tlist[i] * NE + e] = 1.f;
    }
}

// ============ softmax + mask + renorm; transposed block partials ============
__global__ void __launch_bounds__(256)
softmax_kernel(const float* __restrict__ routing, float* __restrict__ probs)
{
    const int lane = threadIdx.x & 31, w = threadIdx.x >> 5;
    const int t = blockIdx.x * 8 + w;
    __shared__ float sA[8][32], sB[8][32];

    const float l0 = g_logits[t * NE + lane];
    const float l1 = g_logits[t * NE + 32 + lane];
    const float r0 = routing[(size_t)t * NE + lane];
    const float r1 = routing[(size_t)t * NE + 32 + lane];
    float m = fmaxf(l0, l1);
#pragma unroll
    for (int o = 16; o; o >>= 1) m = fmaxf(m, __shfl_xor_sync(~0u, m, o));
    const float e0 = __expf(l0 - m), e1 = __expf(l1 - m);
    float s = e0 + e1;
#pragma unroll
    for (int o = 16; o; o >>= 1) s += __shfl_xor_sync(~0u, s, o);
    const float q0 = (e0 / s) * r0;
    const float q1 = (e1 / s) * r1;
    float rs = q0 + q1;
#pragma unroll
    for (int o = 16; o; o >>= 1) rs += __shfl_xor_sync(~0u, rs, o);
    const float inv = 1.f / (rs + EPSF);
    const float n0 = q0 * inv, n1 = q1 * inv;
    probs[(size_t)t * NE + lane] = n0;
    probs[(size_t)t * NE + 32 + lane] = n1;

    sA[w][lane] = n0; sB[w][lane] = n1;
    __syncthreads();
    if (w == 0) {
        float a = 0.f;
#pragma unroll
        for (int k = 0; k < 8; k++) a += sA[k][lane];
        g_partT[lane * NPART + blockIdx.x] = a;
    } else if (w == 1) {
        float a = 0.f;
#pragma unroll
        for (int k = 0; k < 8; k++) a += sB[k][lane];
        g_partT[(32 + lane) * NPART + blockIdx.x] = a;
    }
}

// ===================== aux loss =============================================
__global__ void __launch_bounds__(256)
imp_kernel()
{
    __shared__ float red[8];
    const int e = blockIdx.x, tid = threadIdx.x;
    float s = 0.f;
    for (int i = tid; i < NPART; i += 256) s += g_partT[e * NPART + i];
#pragma unroll
    for (int o = 16; o; o >>= 1) s += __shfl_xor_sync(~0u, s, o);
    if ((tid & 31) == 0) red[tid >> 5] = s;
    __syncthreads();
    if (tid == 0) {
        float a = 0.f;
#pragma unroll
        for (int k = 0; k < 8; k++) a += red[k];
        g_imp[e] = a;
    }
}
__global__ void __launch_bounds__(64)
loss_kernel(float* __restrict__ aux)
{
    __shared__ float v[64];
    v[threadIdx.x] = g_imp[threadIdx.x];
    __syncthreads();
    if (threadIdx.x == 0) {
        float m = 0.f;
        for (int i = 0; i < 64; i++) m += v[i];
        m *= (1.f / 64.f);
        float var = 0.f;
        for (int i = 0; i < 64; i++) { const float d = v[i] - m; var += d * d; }
        var *= (1.f / 63.f);
        const float r = sqrtf(var) / (m + EPSF);
        aux[0] = r * r;
    }
}

extern "C" void kernel_launch(void* const* d_in, const int* in_sizes, int n_in,
                              void* d_out, int out_size)
{
    const float* hidden = (const float*)d_in[0];
    const float* gate   = (const float*)d_in[1];
    float* probs   = (float*)d_out;
    float* routing = probs + (size_t)TOK * NE;
    float* aux     = routing + (size_t)TOK * NE;

    build_bfrag<<<256, 256>>>(gate);
    gemm_kernel<<<TOK / BM, 256, STG * STGU * 16>>>(hidden);
    transpose_kernel<<<TOK / 64, 256>>>();
    histA_kernel<<<NE * 8, 256>>>();
    select_kernel<<<NE, 1024>>>(routing);
    softmax_kernel<<<TOK / 8, 256>>>(routing, probs);
    imp_kernel<<<NE, 256>>>();
    loss_kernel<<<1, 64>>>(aux);
}

// round 12
// speedup vs baseline: 1.3630x; 1.0251x over previous
#include <cuda_runtime.h>
#include <cuda_fp16.h>
#include <math.h>
#include <cstdint>

#define TOK  16384
#define HID  4096
#define NE   64
#define CTOP 512
#define EPSF 1e-6f

#define BM   128
#define NKT  (HID / 32)
#define NPART 2048
#define STG  4
#define STGU 512
#define GSMEM 33536          // max(32768 pipeline, 128*65*4 transpose tile)

__device__ float g_logits[TOK * NE];
__device__ float g_partT[NE * NPART];
__device__ float g_imp[NE];
__device__ uint4 g_bfrag[256 * 8 * 32];
__device__ unsigned g_keysT[NE * TOK];        // omap keys, [e][t]
__device__ unsigned g_hist[NE * 256];
__device__ unsigned g_thresh[NE];
__device__ unsigned long long g_tiemask[TOK]; // tie-taken bit per (t,e)

// ---------------------------- helpers ---------------------------------------
__device__ __forceinline__ uint32_t smem_u32(const void* p) {
    uint32_t a;
    asm("{ .reg .u64 t; cvta.to.shared.u64 t, %1; cvt.u32.u64 %0, t; }"
        : "=r"(a) : "l"(p));
    return a;
}
__device__ __forceinline__ void cp16(uint32_t s, const void* g) {
    asm volatile("cp.async.cg.shared.global [%0], [%1], 16;" :: "r"(s), "l"(g));
}
#define CP_COMMIT() asm volatile("cp.async.commit_group;" ::: "memory")
#define CP_WAIT2()  asm volatile("cp.async.wait_group 2;" ::: "memory")
__device__ __forceinline__ void mma_f32(float* c, const uint32_t* a,
                                        uint32_t b0, uint32_t b1) {
    asm volatile(
        "mma.sync.aligned.m16n8k16.row.col.f32.f16.f16.f32 "
        "{%0,%1,%2,%3}, {%4,%5,%6,%7}, {%8,%9}, {%0,%1,%2,%3};"
        : "+f"(c[0]), "+f"(c[1]), "+f"(c[2]), "+f"(c[3])
        : "r"(a[0]), "r"(a[1]), "r"(a[2]), "r"(a[3]), "r"(b0), "r"(b1));
}
__device__ __forceinline__ void mma_f16(uint32_t* c, const uint32_t* a,
                                        uint32_t b0, uint32_t b1) {
    asm volatile(
        "mma.sync.aligned.m16n8k16.row.col.f16.f16.f16.f16 "
        "{%0,%1}, {%2,%3,%4,%5}, {%6,%7}, {%0,%1};"
        : "+r"(c[0]), "+r"(c[1])
        : "r"(a[0]), "r"(a[1]), "r"(a[2]), "r"(a[3]), "r"(b0), "r"(b1));
}
__device__ __forceinline__ void split_f2(float2 v, uint32_t& h, uint32_t& l) {
    __half2 hh = __floats2half2_rn(v.x, v.y);
    float2 hf = __half22float2(hh);
    __half2 ll = __floats2half2_rn(v.x - hf.x, v.y - hf.y);
    h = *reinterpret_cast<uint32_t*>(&hh);
    l = *reinterpret_cast<uint32_t*>(&ll);
}
__device__ __forceinline__ unsigned omap(float f) {
    unsigned u = __float_as_uint(f);
    return (u & 0x80000000u) ? ~u : (u | 0x80000000u);
}

// ------------- pre-kernel: B fragments; zero hist + tiemask -----------------
__global__ void __launch_bounds__(256)
build_bfrag(const float* __restrict__ gate)
{
    const int idx = blockIdx.x * 256 + threadIdx.x;
    if (idx < NE * 256) g_hist[idx] = 0u;
    if (idx >= 16384 && idx < 16384 + TOK) g_tiemask[idx - 16384] = 0ull;
    const int lane = idx & 31, n8 = (idx >> 5) & 7, k16 = idx >> 8;
    const int n = n8 * 8 + (lane >> 2);
    const int k0 = k16 * 16 + (lane & 3) * 2;
    const float* g = gate + (size_t)n * HID + k0;
    const float2 v0 = *reinterpret_cast<const float2*>(g);
    const float2 v1 = *reinterpret_cast<const float2*>(g + 8);
    uint32_t b0h, b0l, b1h, b1l;
    split_f2(v0, b0h, b0l);
    split_f2(v1, b1h, b1l);
    g_bfrag[idx] = make_uint4(b0h, b1h, b0l, b1l);
}

// GEMM (R9-proven) + fused transpose epilogue writing g_keysT ----------------
__global__ void __launch_bounds__(256, 1)
gemm_kernel(const float* __restrict__ A)
{
    extern __shared__ uint4 bsm[];
    const int tid = threadIdx.x, lane = tid & 31, wid = tid >> 5;
    const int bm0 = blockIdx.x * BM;
    const int row = bm0 + wid * 16 + (lane >> 2);
    const uint32_t smb = smem_u32(bsm);

    const float* a0 = A + (size_t)row * HID + (lane & 3) * 2;
    const float* a1 = a0 + 8 * HID;

    float accf[8][4];
    uint32_t acc16[8][2];
#pragma unroll
    for (int n = 0; n < 8; n++) {
#pragma unroll
        for (int i = 0; i < 4; i++) accf[n][i] = 0.f;
        acc16[n][0] = 0u; acc16[n][1] = 0u;
    }
#pragma unroll
    for (int kt = 0; kt < 3; kt++) {
        const uint32_t dst = smb + (uint32_t)(((kt & 3) * STGU + tid) * 16);
        const uint4* src = g_bfrag + (size_t)kt * STGU + tid;
        cp16(dst, src);
        cp16(dst + 256 * 16, src + 256);
        CP_COMMIT();
    }
    float2 cur[8], nxt[8];
#pragma unroll
    for (int ks = 0; ks < 2; ks++) {
        const int o = ks * 16;
        cur[ks * 4 + 0] = *reinterpret_cast<const float2*>(a0 + o);
        cur[ks * 4 + 1] = *reinterpret_cast<const float2*>(a1 + o);
        cur[ks * 4 + 2] = *reinterpret_cast<const float2*>(a0 + o + 8);
        cur[ks * 4 + 3] = *reinterpret_cast<const float2*>(a1 + o + 8);
    }
#pragma unroll 1
    for (int kt = 0; kt < NKT; kt++) {
        if (kt + 1 < NKT) {
            const int base = (kt + 1) * 32;
#pragma unroll
            for (int ks = 0; ks < 2; ks++) {
                const int o = base + ks * 16;
                nxt[ks * 4 + 0] = *reinterpret_cast<const float2*>(a0 + o);
                nxt[ks * 4 + 1] = *reinterpret_cast<const float2*>(a1 + o);
                nxt[ks * 4 + 2] = *reinterpret_cast<const float2*>(a0 + o + 8);
                nxt[ks * 4 + 3] = *reinterpret_cast<const float2*>(a1 + o + 8);
            }
        }
        CP_WAIT2();
        __syncthreads();
        if (kt + 3 < NKT) {
            const uint32_t dst = smb + (uint32_t)((((kt + 3) & 3) * STGU + tid) * 16);
            const uint4* src = g_bfrag + (size_t)(kt + 3) * STGU + tid;
            cp16(dst, src);
            cp16(dst + 256 * 16, src + 256);
        }
        CP_COMMIT();
        const uint32_t stage = smb + (uint32_t)((kt & 3) * STGU * 16);
#pragma unroll
        for (int ks = 0; ks < 2; ks++) {
            uint32_t ah[4], al[4];
#pragma unroll
            for (int j = 0; j < 4; j++)
                split_f2(cur[ks * 4 + j], ah[j], al[j]);
            const uint32_t bbase = stage + (uint32_t)(((ks * 8) * 32 + lane) * 16);
#pragma unroll
            for (int n8 = 0; n8 < 8; n8++) {
                uint4 b;
                asm volatile("ld.shared.v4.u32 {%0,%1,%2,%3}, [%4];"
                             : "=r"(b.x), "=r"(b.y), "=r"(b.z), "=r"(b.w)
                             : "r"(bbase + (uint32_t)(n8 * 32 * 16)));
                mma_f32(accf[n8], ah, b.x, b.y);
                mma_f16(acc16[n8], ah, b.z, b.w);
                mma_f16(acc16[n8], al, b.x, b.y);
            }
        }
        if ((kt & 3) == 3) {
#pragma unroll
            for (int n = 0; n < 8; n++) {
                const float2 lo = __half22float2(*reinterpret_cast<__half2*>(&acc16[n][0]));
                const float2 hi = __half22float2(*reinterpret_cast<__half2*>(&acc16[n][1]));
                accf[n][0] += lo.x; accf[n][1] += lo.y;
                accf[n][2] += hi.x; accf[n][3] += hi.y;
                acc16[n][0] = 0u; acc16[n][1] = 0u;
            }
        }
#pragma unroll
        for (int j = 0; j < 8; j++) cur[j] = nxt[j];
    }
    const int gid = lane >> 2;
    const int col = (lane & 3) * 2;
    const int row0 = bm0 + wid * 16 + gid;
#pragma unroll
    for (int n = 0; n < 8; n++) {
        *reinterpret_cast<float2*>(&g_logits[row0 * NE + n * 8 + col]) =
            make_float2(accf[n][0], accf[n][1]);
        *reinterpret_cast<float2*>(&g_logits[(row0 + 8) * NE + n * 8 + col]) =
            make_float2(accf[n][2], accf[n][3]);
    }

    // fused transpose: regs -> smem tile -> coalesced g_keysT
    __syncthreads();                      // pipeline smem fully consumed
    float* tile = reinterpret_cast<float*>(bsm);   // [128][65]
    const int tl = wid * 16 + gid;
#pragma unroll
    for (int n = 0; n < 8; n++) {
        tile[tl * 65 + n * 8 + col]           = accf[n][0];
        tile[tl * 65 + n * 8 + col + 1]       = accf[n][1];
        tile[(tl + 8) * 65 + n * 8 + col]     = accf[n][2];
        tile[(tl + 8) * 65 + n * 8 + col + 1] = accf[n][3];
    }
    __syncthreads();
#pragma unroll
    for (int ee = 0; ee < 8; ee++) {
        const int e = wid * 8 + ee;
#pragma unroll
        for (int i = 0; i < 4; i++)
            g_keysT[(size_t)e * TOK + bm0 + i * 32 + lane] =
                omap(tile[(i * 32 + lane) * 65 + e]);
    }
}

// -------- split first-pass histogram (top byte), 8 blocks per expert --------
__global__ void __launch_bounds__(256)
histA_kernel()
{
    __shared__ unsigned h[256];
    const int e = blockIdx.x >> 3, q = blockIdx.x & 7;
    const int tid = threadIdx.x;
    h[tid] = 0u;
    __syncthreads();
    const unsigned* keys = g_keysT + (size_t)e * TOK + q * (TOK / 8);
#pragma unroll
    for (int i = 0; i < (TOK / 8) / 256; i++)
        atomicAdd(&h[keys[i * 256 + tid] >> 24], 1u);
    __syncthreads();
    atomicAdd(&g_hist[e * 256 + tid], h[tid]);
}

// -------- digit pick via suffix scan (256 bins), called by 512 threads ------
__device__ __forceinline__ void pick_digit(unsigned* h, unsigned* ca, unsigned* cb,
                                           unsigned* s_pref, unsigned* s_rem,
                                           int tid, bool first)
{
    if (tid < 256) ca[tid] = h[tid];
    __syncthreads();
    unsigned* src = ca; unsigned* dst = cb;
    for (int s = 1; s < 256; s <<= 1) {
        if (tid < 256) dst[tid] = src[tid] + ((tid + s < 256) ? src[tid + s] : 0u);
        __syncthreads();
        unsigned* tmp = src; src = dst; dst = tmp;
    }
    if (tid < 256) {
        const unsigned rem = *s_rem;
        const unsigned cd = src[tid];
        const unsigned cn = (tid < 255) ? src[tid + 1] : 0u;
        if (cd >= rem && cn < rem) {
            *s_pref = first ? (unsigned)tid : ((*s_pref << 8) | (unsigned)tid);
            *s_rem = rem - cn;
        }
    }
    __syncthreads();
}

// -------- select: compact boundary bin, radix on smem list, emit thresh+ties
__global__ void __launch_bounds__(512)
select_kernel()
{
    __shared__ unsigned h[256], ca[256], cb[256];
    __shared__ unsigned lk[2048];
    __shared__ unsigned short li[2048];
    __shared__ unsigned tlist[64];
    __shared__ unsigned s_pref, s_rem, s_cnt, s_tc;
    const int e = blockIdx.x, tid = threadIdx.x;
    const unsigned* keys = g_keysT + (size_t)e * TOK;

    if (tid == 0) { s_rem = CTOP; s_cnt = 0u; s_tc = 0u; }
    if (tid < 256) h[tid] = g_hist[e * 256 + tid];
    __syncthreads();
    pick_digit(h, ca, cb, &s_pref, &s_rem, tid, true);

    const unsigned d1 = s_pref;
#pragma unroll 4
    for (int i = 0; i < TOK / 512; i++) {
        const int t = i * 512 + tid;
        const unsigned u = keys[t];
        if ((u >> 24) == d1) {
            const unsigned p = atomicAdd(&s_cnt, 1u);
            if (p < 2048u) { lk[p] = u; li[p] = (unsigned short)t; }
        }
    }
    __syncthreads();
    const int n = (s_cnt < 2048u) ? (int)s_cnt : 2048;

    for (int b = 2; b >= 0; b--) {
        if (tid < 256) h[tid] = 0u;
        __syncthreads();
        const unsigned pref = s_pref;
        const int shift = (b + 1) * 8;
        for (int j = tid; j < n; j += 512) {
            const unsigned u = lk[j];
            if ((u >> shift) == pref) atomicAdd(&h[(u >> (b * 8)) & 255u], 1u);
        }
        __syncthreads();
        pick_digit(h, ca, cb, &s_pref, &s_rem, tid, false);
    }

    const unsigned tkey = s_pref;
    for (int j = tid; j < n; j += 512) {
        if (lk[j] == tkey) {
            const unsigned p = atomicAdd(&s_tc, 1u);
            if (p < 64u) tlist[p] = li[j];
        }
    }
    __syncthreads();
    if (tid == 0) {
        int nt = (int)s_tc; if (nt > 64) nt = 64;
        for (int i = 1; i < nt; i++) {
            const unsigned v = tlist[i]; int j = i - 1;
            while (j >= 0 && tlist[j] > v) { tlist[j + 1] = tlist[j]; j--; }
            tlist[j + 1] = v;
        }
        int take = (int)s_rem; if (take > nt) take = nt;
        for (int i = 0; i < take; i++)
            atomicOr(&g_tiemask[tlist[i]], 1ull << e);
        g_thresh[e] = tkey;
    }
}

// ===== softmax: reconstruct routing from thresh+ties; write routing+probs ===
__global__ void __launch_bounds__(256)
softmax_kernel(float* __restrict__ routing, float* __restrict__ probs)
{
    const int lane = threadIdx.x & 31, w = threadIdx.x >> 5;
    const int t = blockIdx.x * 8 + w;
    __shared__ float sA[8][32], sB[8][32];

    const float l0 = g_logits[t * NE + lane];
    const float l1 = g_logits[t * NE + 32 + lane];
    const unsigned tk0 = g_thresh[lane];
    const unsigned tk1 = g_thresh[32 + lane];
    const unsigned long long msk = g_tiemask[t];
    const float r0 = (omap(l0) > tk0 || ((msk >> lane) & 1ull)) ? 1.f : 0.f;
    const float r1 = (omap(l1) > tk1 || ((msk >> (32 + lane)) & 1ull)) ? 1.f : 0.f;

    float m = fmaxf(l0, l1);
#pragma unroll
    for (int o = 16; o; o >>= 1) m = fmaxf(m, __shfl_xor_sync(~0u, m, o));
    const float e0 = __expf(l0 - m), e1 = __expf(l1 - m);
    float s = e0 + e1;
#pragma unroll
    for (int o = 16; o; o >>= 1) s += __shfl_xor_sync(~0u, s, o);
    const float q0 = (e0 / s) * r0;
    const float q1 = (e1 / s) * r1;
    float rs = q0 + q1;
#pragma unroll
    for (int o = 16; o; o >>= 1) rs += __shfl_xor_sync(~0u, rs, o);
    const float inv = 1.f / (rs + EPSF);
    const float n0 = q0 * inv, n1 = q1 * inv;
    routing[(size_t)t * NE + lane] = r0;
    routing[(size_t)t * NE + 32 + lane] = r1;
    probs[(size_t)t * NE + lane] = n0;
    probs[(size_t)t * NE + 32 + lane] = n1;

    sA[w][lane] = n0; sB[w][lane] = n1;
    __syncthreads();
    if (w == 0) {
        float a = 0.f;
#pragma unroll
        for (int k = 0; k < 8; k++) a += sA[k][lane];
        g_partT[lane * NPART + blockIdx.x] = a;
    } else if (w == 1) {
        float a = 0.f;
#pragma unroll
        for (int k = 0; k < 8; k++) a += sB[k][lane];
        g_partT[(32 + lane) * NPART + blockIdx.x] = a;
    }
}

// ===================== aux loss =============================================
__global__ void __launch_bounds__(256)
imp_kernel()
{
    __shared__ float red[8];
    const int e = blockIdx.x, tid = threadIdx.x;
    float s = 0.f;
    for (int i = tid; i < NPART; i += 256) s += g_partT[e * NPART + i];
#pragma unroll
    for (int o = 16; o; o >>= 1) s += __shfl_xor_sync(~0u, s, o);
    if ((tid & 31) == 0) red[tid >> 5] = s;
    __syncthreads();
    if (tid == 0) {
        float a = 0.f;
#pragma unroll
        for (int k = 0; k < 8; k++) a += red[k];
        g_imp[e] = a;
    }
}
__global__ void __launch_bounds__(64)
loss_kernel(float* __restrict__ aux)
{
    __shared__ float v[64];
    v[threadIdx.x] = g_imp[threadIdx.x];
    __syncthreads();
    if (threadIdx.x == 0) {
        float m = 0.f;
        for (int i = 0; i < 64; i++) m += v[i];
        m *= (1.f / 64.f);
        float var = 0.f;
        for (int i = 0; i < 64; i++) { const float d = v[i] - m; var += d * d; }
        var *= (1.f / 63.f);
        const float r = sqrtf(var) / (m + EPSF);
        aux[0] = r * r;
    }
}

extern "C" void kernel_launch(void* const* d_in, const int* in_sizes, int n_in,
                              void* d_out, int out_size)
{
    const float* hidden = (const float*)d_in[0];
    const float* gate   = (const float*)d_in[1];
    float* probs   = (float*)d_out;
    float* routing = probs + (size_t)TOK * NE;
    float* aux     = routing + (size_t)TOK * NE;

    build_bfrag<<<256, 256>>>(gate);
    gemm_kernel<<<TOK / BM, 256, GSMEM>>>(hidden);
    histA_kernel<<<NE * 8, 256>>>();
    select_kernel<<<NE, 512>>>();
    softmax_kernel<<<TOK / 8, 256>>>(routing, probs);
    imp_kernel<<<NE, 256>>>();
    loss_kernel<<<1, 64>>>(aux);
}